// round 13
// baseline (speedup 1.0000x reference)
#include <cuda_runtime.h>

// Problem constants
#define T_TOKENS 32768
#define E_DIM    512
#define GROUPS   4
#define DIM      128
#define KCODES   512

// Tiling: half-height CTAs, 2 resident per SM
#define MT       64        // tokens per block
#define KT       128       // codes per K-tile
#define THREADS  128
#define XS_STRIDE 132
#define WS_STRIDE 132

__device__ float  g_wsq[GROUPS * KCODES];
__device__ double g_loss_acc;

__global__ void vq_init_kernel() { g_loss_acc = 0.0; }

__global__ void vq_finalize_kernel(float* out, long long loss_index) {
    // vq_loss = sum_g (beta*commit + embed) = 1.25 * total_sq / (16*2048*128)
    out[loss_index] = (float)(g_loss_acc * (1.25 / 4194304.0));
}

// exact wsq per code row — identical sequential fp32 FMA chain as the in-kernel
// round-3 version (same order => bit-identical values => same argmins).
__global__ void vq_prep_kernel(const float* __restrict__ w0, const float* __restrict__ w1,
                               const float* __restrict__ w2, const float* __restrict__ w3)
{
    int r = blockIdx.x * blockDim.x + threadIdx.x;
    if (r >= GROUPS * KCODES) return;
    int g = r >> 9, k = r & (KCODES - 1);
    const float* W = (g == 0) ? w0 : (g == 1) ? w1 : (g == 2) ? w2 : w3;
    const float* row = W + (size_t)k * DIM;
    float s = 0.0f;
    #pragma unroll 4
    for (int d = 0; d < DIM; ++d) s = fmaf(row[d], row[d], s);
    g_wsq[r] = s;
}

__global__ __launch_bounds__(THREADS, 2)
void vq_main_kernel(const float* __restrict__ latents,
                    const float* __restrict__ w0,
                    const float* __restrict__ w1,
                    const float* __restrict__ w2,
                    const float* __restrict__ w3,
                    float* __restrict__ out)
{
    extern __shared__ float smem[];
    float* xs  = smem;                       // MT * XS_STRIDE
    float* ws  = xs + MT * XS_STRIDE;        // KT * WS_STRIDE
    float* xsq = ws + KT * WS_STRIDE;        // MT
    float* wsq = xsq + MT;                   // KCODES
    int*   bestk_sm = (int*)(wsq + KCODES);  // MT
    double* red = (double*)(bestk_sm + MT);  // 4

    const int g  = blockIdx.y;
    const int t0 = blockIdx.x * MT;
    const float* __restrict__ W = (g == 0) ? w0 : (g == 1) ? w1 : (g == 2) ? w2 : w3;

    const int tid = threadIdx.x;
    const int tx  = tid & 15;   // code lane  (16)
    const int ty  = tid >> 4;   // token lane (8)

    // ---- load x tile (64 tokens x 128 dims) + wsq ----
    {
        const int d4 = tid & 31;      // float4 index within row
        const int mb = tid >> 5;      // 0..3
        #pragma unroll
        for (int r = 0; r < MT / 4; ++r) {
            int m = mb + r * 4;
            float4 v = *(const float4*)(latents + (size_t)(t0 + m) * E_DIM + g * DIM + d4 * 4);
            *(float4*)(xs + m * XS_STRIDE + d4 * 4) = v;
        }
    }
    for (int i = tid; i < KCODES; i += THREADS) wsq[i] = g_wsq[g * KCODES + i];
    __syncthreads();

    // ---- x_sq per token (sequential fp32, ref order) ----
    if (tid < MT) {
        const float* row = xs + tid * XS_STRIDE;
        float s = 0.0f;
        #pragma unroll
        for (int d = 0; d < DIM; ++d) s = fmaf(row[d], row[d], s);
        xsq[tid] = s;
    }
    __syncthreads();

    // cache this thread's 8 token x_sq values (tokens ty + 8*i)
    float my_xsq[8];
    #pragma unroll
    for (int i = 0; i < 8; ++i) my_xsq[i] = xsq[ty + 8 * i];

    float bestd[8];
    int   bestk[8];
    #pragma unroll
    for (int i = 0; i < 8; ++i) { bestd[i] = 3.402823466e38f; bestk[i] = 0; }

    for (int kt = 0; kt < KCODES / KT; ++kt) {
        __syncthreads();  // previous tile's ws readers done
        // ---- load w tile (128 codes x 128 dims) ----
        {
            const int d4 = tid & 31;
            const int kb = tid >> 5;      // 0..3
            #pragma unroll
            for (int r = 0; r < KT / 4; ++r) {
                int k = kb + r * 4;
                float4 v = *(const float4*)(W + (size_t)(kt * KT + k) * DIM + d4 * 4);
                *(float4*)(ws + k * WS_STRIDE + d4 * 4) = v;
            }
        }
        __syncthreads();

        // ---- 8x8 register-tile dot products (identical inner loop to champion) ----
        float acc[8][8];
        #pragma unroll
        for (int i = 0; i < 8; ++i)
            #pragma unroll
            for (int j = 0; j < 8; ++j) acc[i][j] = 0.0f;

        for (int d4 = 0; d4 < DIM / 4; ++d4) {
            float4 xf[8];
            #pragma unroll
            for (int i = 0; i < 8; ++i)
                xf[i] = *(const float4*)(xs + (ty + 8 * i) * XS_STRIDE + d4 * 4);
            #pragma unroll
            for (int j = 0; j < 8; ++j) {
                float4 wf = *(const float4*)(ws + (tx + 16 * j) * WS_STRIDE + d4 * 4);
                #pragma unroll
                for (int i = 0; i < 8; ++i) {
                    acc[i][j] = fmaf(xf[i].x, wf.x, acc[i][j]);
                    acc[i][j] = fmaf(xf[i].y, wf.y, acc[i][j]);
                    acc[i][j] = fmaf(xf[i].z, wf.z, acc[i][j]);
                    acc[i][j] = fmaf(xf[i].w, wf.w, acc[i][j]);
                }
            }
        }

        // ---- distances + running argmin (first-index tie break like jnp.argmin) ----
        #pragma unroll
        for (int j = 0; j < 8; ++j) {
            int   kg    = kt * KT + tx + 16 * j;
            float t_wsq = wsq[kg];
            #pragma unroll
            for (int i = 0; i < 8; ++i) {
                float t  = my_xsq[i] + t_wsq;           // fl(x_sq + w_sq)
                float dd = fmaf(-2.0f, acc[i][j], t);   // fl(t - 2*cross): exact ref formula
                if (dd < bestd[i] || (dd == bestd[i] && kg < bestk[i])) {
                    bestd[i] = dd; bestk[i] = kg;
                }
            }
        }
    }

    // ---- reduce argmin across the 16 code-lanes ----
    #pragma unroll
    for (int i = 0; i < 8; ++i) {
        float bd = bestd[i]; int bk = bestk[i];
        #pragma unroll
        for (int off = 1; off < 16; off <<= 1) {
            float od = __shfl_xor_sync(0xffffffffu, bd, off);
            int   ok = __shfl_xor_sync(0xffffffffu, bk, off);
            if (od < bd || (od == bd && ok < bk)) { bd = od; bk = ok; }
        }
        if (tx == 0) bestk_sm[ty + 8 * i] = bk;
    }
    __syncthreads();

    // ---- epilogue: gather codeword, straight-through output, loss ----
    double lsum = 0.0;
    #pragma unroll
    for (int r = 0; r < (MT * 32) / THREADS; ++r) {  // 16 iters
        int idx = tid + r * THREADS;
        int m   = idx >> 5;
        int d4  = idx & 31;
        int bk  = bestk_sm[m];
        float4 q = *(const float4*)(W + (size_t)bk * DIM + d4 * 4);
        float4 x = *(const float4*)(xs + m * XS_STRIDE + d4 * 4);
        float dx = q.x - x.x, dy = q.y - x.y, dz = q.z - x.z, dw = q.w - x.w;
        float4 o;
        o.x = x.x + dx; o.y = x.y + dy; o.z = x.z + dz; o.w = x.w + dw;  // x + (q - x), as ref
        *(float4*)(out + (size_t)(t0 + m) * E_DIM + g * DIM + d4 * 4) = o;
        lsum += (double)dx * dx + (double)dy * dy + (double)dz * dz + (double)dw * dw;
    }

    // ---- block loss reduction ----
    #pragma unroll
    for (int off = 16; off; off >>= 1)
        lsum += __shfl_xor_sync(0xffffffffu, lsum, off);
    if ((tid & 31) == 0) red[tid >> 5] = lsum;
    __syncthreads();
    if (tid == 0) {
        double s = red[0] + red[1] + red[2] + red[3];
        atomicAdd(&g_loss_acc, s);
    }
}

extern "C" void kernel_launch(void* const* d_in, const int* in_sizes, int n_in,
                              void* d_out, int out_size) {
    const float* latents = (const float*)d_in[0];
    const float* w1 = (const float*)d_in[1];
    const float* w2 = (const float*)d_in[2];
    const float* w3 = (const float*)d_in[3];
    const float* w4 = (const float*)d_in[4];
    float* out = (float*)d_out;

    // smem: xs + ws + xsq + wsq + bestk + red  (~104 KB -> 2 CTAs/SM)
    size_t smem_bytes = (size_t)(MT * XS_STRIDE + KT * WS_STRIDE + MT + KCODES) * sizeof(float)
                      + MT * sizeof(int) + 4 * sizeof(double);
    cudaFuncSetAttribute(vq_main_kernel, cudaFuncAttributeMaxDynamicSharedMemorySize,
                         (int)smem_bytes);

    vq_init_kernel<<<1, 1>>>();
    vq_prep_kernel<<<(GROUPS * KCODES + 255) / 256, 256>>>(w1, w2, w3, w4);
    dim3 grid(T_TOKENS / MT, GROUPS);
    vq_main_kernel<<<grid, THREADS, smem_bytes>>>(latents, w1, w2, w3, w4, out);
    vq_finalize_kernel<<<1, 1>>>(out, (long long)out_size - 1);
}

// round 14
// speedup vs baseline: 1.0094x; 1.0094x over previous
#include <cuda_runtime.h>

// Problem constants
#define T_TOKENS 32768     // 16*2048 tokens
#define E_DIM    512       // embedding dim
#define GROUPS   4
#define DIM      128       // per-group dim
#define KCODES   512       // codes per group

// Tiling
#define MT       128       // tokens per block
#define KT       128       // codes per K-tile
#define THREADS  256
#define XS_STRIDE 132      // padded smem row stride (floats)
#define WS_STRIDE 132

__device__ float  g_wsq[GROUPS * KCODES];
__device__ double g_loss_acc;

__global__ void vq_init_kernel() { g_loss_acc = 0.0; }

__global__ void vq_finalize_kernel(float* out, long long loss_index) {
    // vq_loss = sum_g (beta*commit + embed) = 1.25 * total_sq / (16*2048*128)
    out[loss_index] = (float)(g_loss_acc * (1.25 / 4194304.0));
}

// exact wsq per code row — identical sequential fp32 FMA chain as the in-kernel
// version it replaced (same order => bit-identical values => same argmins).
__global__ void vq_prep_kernel(const float* __restrict__ w0, const float* __restrict__ w1,
                               const float* __restrict__ w2, const float* __restrict__ w3)
{
    int r = blockIdx.x * blockDim.x + threadIdx.x;
    if (r >= GROUPS * KCODES) return;
    int g = r >> 9, k = r & (KCODES - 1);
    const float* W = (g == 0) ? w0 : (g == 1) ? w1 : (g == 2) ? w2 : w3;
    const float* row = W + (size_t)k * DIM;
    float s = 0.0f;
    #pragma unroll 4
    for (int d = 0; d < DIM; ++d) s = fmaf(row[d], row[d], s);
    g_wsq[r] = s;
}

__global__ __launch_bounds__(THREADS, 1)
void vq_main_kernel(const float* __restrict__ latents,
                    const float* __restrict__ w0,
                    const float* __restrict__ w1,
                    const float* __restrict__ w2,
                    const float* __restrict__ w3,
                    float* __restrict__ out)
{
    extern __shared__ float smem[];
    float* xs  = smem;                       // MT * XS_STRIDE
    float* ws  = xs + MT * XS_STRIDE;        // KT * WS_STRIDE
    float* xsq = ws + KT * WS_STRIDE;        // MT
    float* wsq = xsq + MT;                   // KCODES (all 512, loaded once)
    int*   bestk_sm = (int*)(wsq + KCODES);  // MT
    double* red = (double*)(bestk_sm + MT);  // 8

    const int g  = blockIdx.y;
    const int t0 = blockIdx.x * MT;
    const float* __restrict__ W = (g == 0) ? w0 : (g == 1) ? w1 : (g == 2) ? w2 : w3;

    const int tid = threadIdx.x;
    const int tx  = tid & 15;   // code lane
    const int ty  = tid >> 4;   // token lane

    // ---- load x tile (tokens t0..t0+127, dims of group g) + wsq ----
    {
        const int d4 = tid & 31;      // float4 index within row
        const int mb = tid >> 5;      // 0..7
        #pragma unroll
        for (int r = 0; r < MT / 8; ++r) {
            int m = mb + r * 8;
            float4 v = *(const float4*)(latents + (size_t)(t0 + m) * E_DIM + g * DIM + d4 * 4);
            *(float4*)(xs + m * XS_STRIDE + d4 * 4) = v;
        }
    }
    for (int i = tid; i < KCODES; i += THREADS) wsq[i] = g_wsq[g * KCODES + i];
    __syncthreads();

    // ---- x_sq per token (sequential fp32, mirrors ref semantics) ----
    if (tid < MT) {
        const float* row = xs + tid * XS_STRIDE;
        float s = 0.0f;
        #pragma unroll
        for (int d = 0; d < DIM; ++d) s = fmaf(row[d], row[d], s);
        xsq[tid] = s;
    }
    __syncthreads();

    // cache this thread's 8 token x_sq values
    float my_xsq[8];
    #pragma unroll
    for (int i = 0; i < 8; ++i) my_xsq[i] = xsq[ty + 16 * i];

    float bestd[8];
    int   bestk[8];
    #pragma unroll
    for (int i = 0; i < 8; ++i) { bestd[i] = 3.402823466e38f; bestk[i] = 0; }

    for (int kt = 0; kt < KCODES / KT; ++kt) {
        __syncthreads();  // previous tile's ws readers done
        // ---- load w tile ----
        {
            const int d4 = tid & 31;
            const int kb = tid >> 5;
            #pragma unroll
            for (int r = 0; r < KT / 8; ++r) {
                int k = kb + r * 8;
                float4 v = *(const float4*)(W + (size_t)(kt * KT + k) * DIM + d4 * 4);
                *(float4*)(ws + k * WS_STRIDE + d4 * 4) = v;
            }
        }
        __syncthreads();

        // ---- 8x8 register-tile dot products ----
        float acc[8][8];
        #pragma unroll
        for (int i = 0; i < 8; ++i)
            #pragma unroll
            for (int j = 0; j < 8; ++j) acc[i][j] = 0.0f;

        for (int d4 = 0; d4 < DIM / 4; ++d4) {
            float4 xf[8];
            #pragma unroll
            for (int i = 0; i < 8; ++i)
                xf[i] = *(const float4*)(xs + (ty + 16 * i) * XS_STRIDE + d4 * 4);
            #pragma unroll
            for (int j = 0; j < 8; ++j) {
                float4 wf = *(const float4*)(ws + (tx + 16 * j) * WS_STRIDE + d4 * 4);
                #pragma unroll
                for (int i = 0; i < 8; ++i) {
                    acc[i][j] = fmaf(xf[i].x, wf.x, acc[i][j]);
                    acc[i][j] = fmaf(xf[i].y, wf.y, acc[i][j]);
                    acc[i][j] = fmaf(xf[i].z, wf.z, acc[i][j]);
                    acc[i][j] = fmaf(xf[i].w, wf.w, acc[i][j]);
                }
            }
        }

        // ---- distances + running argmin (first-index tie break like jnp.argmin) ----
        #pragma unroll
        for (int j = 0; j < 8; ++j) {
            int   kk    = tx + 16 * j;
            int   kg    = kt * KT + kk;
            float t_wsq = wsq[kg];
            #pragma unroll
            for (int i = 0; i < 8; ++i) {
                float t  = my_xsq[i] + t_wsq;           // ref: x_sq + w_sq
                float dd = fmaf(-2.0f, acc[i][j], t);   // == fl(t - 2*cross), matches ref formula
                if (dd < bestd[i] || (dd == bestd[i] && kg < bestk[i])) {
                    bestd[i] = dd; bestk[i] = kg;
                }
            }
        }
    }

    // ---- reduce argmin across the 16 code-lanes ----
    #pragma unroll
    for (int i = 0; i < 8; ++i) {
        float bd = bestd[i]; int bk = bestk[i];
        #pragma unroll
        for (int off = 1; off < 16; off <<= 1) {
            float od = __shfl_xor_sync(0xffffffffu, bd, off);
            int   ok = __shfl_xor_sync(0xffffffffu, bk, off);
            if (od < bd || (od == bd && ok < bk)) { bd = od; bk = ok; }
        }
        if (tx == 0) bestk_sm[ty + 16 * i] = bk;
    }
    __syncthreads();

    // ---- epilogue: gather codeword, write straight-through output, accumulate loss ----
    double lsum = 0.0;
    #pragma unroll
    for (int r = 0; r < (MT * 32) / THREADS; ++r) {  // 16 iters
        int idx = tid + r * THREADS;
        int m   = idx >> 5;
        int d4  = idx & 31;
        int bk  = bestk_sm[m];
        float4 q = *(const float4*)(W + (size_t)bk * DIM + d4 * 4);
        float4 x = *(const float4*)(xs + m * XS_STRIDE + d4 * 4);
        float dx = q.x - x.x, dy = q.y - x.y, dz = q.z - x.z, dw = q.w - x.w;
        float4 o;
        o.x = x.x + dx; o.y = x.y + dy; o.z = x.z + dz; o.w = x.w + dw;  // x + (q - x), as ref
        *(float4*)(out + (size_t)(t0 + m) * E_DIM + g * DIM + d4 * 4) = o;
        lsum += (double)dx * dx + (double)dy * dy + (double)dz * dz + (double)dw * dw;
    }

    // ---- block loss reduction ----
    #pragma unroll
    for (int off = 16; off; off >>= 1)
        lsum += __shfl_xor_sync(0xffffffffu, lsum, off);
    if ((tid & 31) == 0) red[tid >> 5] = lsum;
    __syncthreads();
    if (tid == 0) {
        double s = 0.0;
        #pragma unroll
        for (int w = 0; w < THREADS / 32; ++w) s += red[w];
        atomicAdd(&g_loss_acc, s);
    }
}

extern "C" void kernel_launch(void* const* d_in, const int* in_sizes, int n_in,
                              void* d_out, int out_size) {
    const float* latents = (const float*)d_in[0];
    const float* w1 = (const float*)d_in[1];
    const float* w2 = (const float*)d_in[2];
    const float* w3 = (const float*)d_in[3];
    const float* w4 = (const float*)d_in[4];
    float* out = (float*)d_out;

    // smem: xs + ws + xsq + wsq + bestk + red
    size_t smem_bytes = (size_t)(MT * XS_STRIDE + KT * WS_STRIDE + MT + KCODES) * sizeof(float)
                      + MT * sizeof(int) + 8 * sizeof(double);
    cudaFuncSetAttribute(vq_main_kernel, cudaFuncAttributeMaxDynamicSharedMemorySize,
                         (int)smem_bytes);

    vq_init_kernel<<<1, 1>>>();
    vq_prep_kernel<<<(GROUPS * KCODES + 255) / 256, 256>>>(w1, w2, w3, w4);
    dim3 grid(T_TOKENS / MT, GROUPS);
    vq_main_kernel<<<grid, THREADS, smem_bytes>>>(latents, w1, w2, w3, w4, out);
    vq_finalize_kernel<<<1, 1>>>(out, (long long)out_size - 1);
}

// round 15
// speedup vs baseline: 1.0146x; 1.0052x over previous
#include <cuda_runtime.h>

// Problem constants
#define T_TOKENS 32768     // 16*2048 tokens
#define E_DIM    512       // embedding dim
#define GROUPS   4
#define DIM      128       // per-group dim
#define KCODES   512       // codes per group

// Tiling: 8 tokens x 16 codes per thread, 2 K-tiles of 256 codes
#define MT       128       // tokens per block
#define KT       256       // codes per K-tile
#define THREADS  256
#define XS_STRIDE 132      // padded smem row stride (floats)
#define WS_STRIDE 132

__device__ float  g_wsq[GROUPS * KCODES];
__device__ double g_loss_acc;

__global__ void vq_init_kernel() { g_loss_acc = 0.0; }

__global__ void vq_finalize_kernel(float* out, long long loss_index) {
    // vq_loss = sum_g (beta*commit + embed) = 1.25 * total_sq / (16*2048*128)
    out[loss_index] = (float)(g_loss_acc * (1.25 / 4194304.0));
}

// exact wsq per code row — identical sequential fp32 FMA chain as the in-kernel
// version it replaced (same order => bit-identical values => same argmins).
__global__ void vq_prep_kernel(const float* __restrict__ w0, const float* __restrict__ w1,
                               const float* __restrict__ w2, const float* __restrict__ w3)
{
    int r = blockIdx.x * blockDim.x + threadIdx.x;
    if (r >= GROUPS * KCODES) return;
    int g = r >> 9, k = r & (KCODES - 1);
    const float* W = (g == 0) ? w0 : (g == 1) ? w1 : (g == 2) ? w2 : w3;
    const float* row = W + (size_t)k * DIM;
    float s = 0.0f;
    #pragma unroll 4
    for (int d = 0; d < DIM; ++d) s = fmaf(row[d], row[d], s);
    g_wsq[r] = s;
}

__global__ __launch_bounds__(THREADS, 1)
void vq_main_kernel(const float* __restrict__ latents,
                    const float* __restrict__ w0,
                    const float* __restrict__ w1,
                    const float* __restrict__ w2,
                    const float* __restrict__ w3,
                    float* __restrict__ out)
{
    extern __shared__ float smem[];
    float* xs  = smem;                       // MT * XS_STRIDE       (16896 f)
    float* ws  = xs + MT * XS_STRIDE;        // KT * WS_STRIDE       (33792 f)
    float* xsq = ws + KT * WS_STRIDE;        // MT
    float* wsq = xsq + MT;                   // KCODES
    int*   bestk_sm = (int*)(wsq + KCODES);  // MT
    double* red = (double*)(bestk_sm + MT);  // 8

    const int g  = blockIdx.y;
    const int t0 = blockIdx.x * MT;
    const float* __restrict__ W = (g == 0) ? w0 : (g == 1) ? w1 : (g == 2) ? w2 : w3;

    const int tid = threadIdx.x;
    const int tx  = tid & 15;   // code lane (16 lanes x 16 codes each = 256 codes/tile)
    const int ty  = tid >> 4;   // token lane (16 lanes x 8 tokens each = 128 tokens)

    // ---- load x tile + wsq ----
    {
        const int d4 = tid & 31;      // float4 index within row
        const int mb = tid >> 5;      // 0..7
        #pragma unroll
        for (int r = 0; r < MT / 8; ++r) {
            int m = mb + r * 8;
            float4 v = *(const float4*)(latents + (size_t)(t0 + m) * E_DIM + g * DIM + d4 * 4);
            *(float4*)(xs + m * XS_STRIDE + d4 * 4) = v;
        }
    }
    for (int i = tid; i < KCODES; i += THREADS) wsq[i] = g_wsq[g * KCODES + i];
    __syncthreads();

    // ---- x_sq per token (sequential fp32, mirrors ref semantics) ----
    if (tid < MT) {
        const float* row = xs + tid * XS_STRIDE;
        float s = 0.0f;
        #pragma unroll
        for (int d = 0; d < DIM; ++d) s = fmaf(row[d], row[d], s);
        xsq[tid] = s;
    }
    __syncthreads();

    // cache this thread's 8 token x_sq values
    float my_xsq[8];
    #pragma unroll
    for (int i = 0; i < 8; ++i) my_xsq[i] = xsq[ty + 16 * i];

    float bestd[8];
    int   bestk[8];
    #pragma unroll
    for (int i = 0; i < 8; ++i) { bestd[i] = 3.402823466e38f; bestk[i] = 0; }

    for (int kt = 0; kt < KCODES / KT; ++kt) {   // 2 tiles
        __syncthreads();  // previous tile's ws readers done
        // ---- load w tile (256 codes x 128 dims) ----
        {
            const int d4 = tid & 31;
            const int kb = tid >> 5;
            #pragma unroll
            for (int r = 0; r < KT / 8; ++r) {
                int k = kb + r * 8;
                float4 v = *(const float4*)(W + (size_t)(kt * KT + k) * DIM + d4 * 4);
                *(float4*)(ws + k * WS_STRIDE + d4 * 4) = v;
            }
        }
        __syncthreads();

        // ---- 8x16 register-tile dot products ----
        float acc[8][16];
        #pragma unroll
        for (int i = 0; i < 8; ++i)
            #pragma unroll
            for (int j = 0; j < 16; ++j) acc[i][j] = 0.0f;

        for (int d4 = 0; d4 < DIM / 4; ++d4) {
            float4 xf[8];
            #pragma unroll
            for (int i = 0; i < 8; ++i)
                xf[i] = *(const float4*)(xs + (ty + 16 * i) * XS_STRIDE + d4 * 4);
            #pragma unroll
            for (int j = 0; j < 16; ++j) {
                float4 wf = *(const float4*)(ws + (tx + 16 * j) * WS_STRIDE + d4 * 4);
                #pragma unroll
                for (int i = 0; i < 8; ++i) {
                    acc[i][j] = fmaf(xf[i].x, wf.x, acc[i][j]);
                    acc[i][j] = fmaf(xf[i].y, wf.y, acc[i][j]);
                    acc[i][j] = fmaf(xf[i].z, wf.z, acc[i][j]);
                    acc[i][j] = fmaf(xf[i].w, wf.w, acc[i][j]);
                }
            }
        }

        // ---- distances + running argmin (first-index tie break like jnp.argmin) ----
        #pragma unroll
        for (int j = 0; j < 16; ++j) {
            int   kg    = kt * KT + tx + 16 * j;
            float t_wsq = wsq[kg];
            #pragma unroll
            for (int i = 0; i < 8; ++i) {
                float t  = my_xsq[i] + t_wsq;           // fl(x_sq + w_sq)
                float dd = fmaf(-2.0f, acc[i][j], t);   // fl(t - 2*cross): exact ref formula
                if (dd < bestd[i] || (dd == bestd[i] && kg < bestk[i])) {
                    bestd[i] = dd; bestk[i] = kg;
                }
            }
        }
    }

    // ---- reduce argmin across the 16 code-lanes ----
    #pragma unroll
    for (int i = 0; i < 8; ++i) {
        float bd = bestd[i]; int bk = bestk[i];
        #pragma unroll
        for (int off = 1; off < 16; off <<= 1) {
            float od = __shfl_xor_sync(0xffffffffu, bd, off);
            int   ok = __shfl_xor_sync(0xffffffffu, bk, off);
            if (od < bd || (od == bd && ok < bk)) { bd = od; bk = ok; }
        }
        if (tx == 0) bestk_sm[ty + 16 * i] = bk;
    }
    __syncthreads();

    // ---- epilogue: gather codeword, write straight-through output, accumulate loss ----
    double lsum = 0.0;
    #pragma unroll
    for (int r = 0; r < (MT * 32) / THREADS; ++r) {  // 16 iters
        int idx = tid + r * THREADS;
        int m   = idx >> 5;
        int d4  = idx & 31;
        int bk  = bestk_sm[m];
        float4 q = *(const float4*)(W + (size_t)bk * DIM + d4 * 4);
        float4 x = *(const float4*)(xs + m * XS_STRIDE + d4 * 4);
        float dx = q.x - x.x, dy = q.y - x.y, dz = q.z - x.z, dw = q.w - x.w;
        float4 o;
        o.x = x.x + dx; o.y = x.y + dy; o.z = x.z + dz; o.w = x.w + dw;  // x + (q - x), as ref
        *(float4*)(out + (size_t)(t0 + m) * E_DIM + g * DIM + d4 * 4) = o;
        lsum += (double)dx * dx + (double)dy * dy + (double)dz * dz + (double)dw * dw;
    }

    // ---- block loss reduction ----
    #pragma unroll
    for (int off = 16; off; off >>= 1)
        lsum += __shfl_xor_sync(0xffffffffu, lsum, off);
    if ((tid & 31) == 0) red[tid >> 5] = lsum;
    __syncthreads();
    if (tid == 0) {
        double s = 0.0;
        #pragma unroll
        for (int w = 0; w < THREADS / 32; ++w) s += red[w];
        atomicAdd(&g_loss_acc, s);
    }
}

extern "C" void kernel_launch(void* const* d_in, const int* in_sizes, int n_in,
                              void* d_out, int out_size) {
    const float* latents = (const float*)d_in[0];
    const float* w1 = (const float*)d_in[1];
    const float* w2 = (const float*)d_in[2];
    const float* w3 = (const float*)d_in[3];
    const float* w4 = (const float*)d_in[4];
    float* out = (float*)d_out;

    // smem: xs + ws + xsq + wsq + bestk + red  (~206 KB, 1 CTA/SM)
    size_t smem_bytes = (size_t)(MT * XS_STRIDE + KT * WS_STRIDE + MT + KCODES) * sizeof(float)
                      + MT * sizeof(int) + 8 * sizeof(double);
    cudaFuncSetAttribute(vq_main_kernel, cudaFuncAttributeMaxDynamicSharedMemorySize,
                         (int)smem_bytes);

    vq_init_kernel<<<1, 1>>>();
    vq_prep_kernel<<<(GROUPS * KCODES + 255) / 256, 256>>>(w1, w2, w3, w4);
    dim3 grid(T_TOKENS / MT, GROUPS);
    vq_main_kernel<<<grid, THREADS, smem_bytes>>>(latents, w1, w2, w3, w4, out);
    vq_finalize_kernel<<<1, 1>>>(out, (long long)out_size - 1);
}